// round 12
// baseline (speedup 1.0000x reference)
#include <cuda_runtime.h>
#include <cstdint>

#define B 8
#define TE 512
#define TD 256
#define H 256

typedef unsigned long long ull;

// Scratch (device globals: no allocations allowed)
__device__ float g_WeT[B * H * TE];  // [b][h][i]
__device__ float g_Uh [B * TD * H];  // [b][j][h]

__device__ __forceinline__ float tanh_fast(float x) {
    float y;
    asm("tanh.approx.f32 %0, %1;" : "=f"(y) : "f"(x));
    return y;
}

// ---- packed fp32x2 helpers ----
__device__ __forceinline__ ull pk2(float lo, float hi) {
    ull r; asm("mov.b64 %0, {%1, %2};" : "=l"(r) : "f"(lo), "f"(hi)); return r;
}
__device__ __forceinline__ ull fma2(ull a, ull b, ull c) {
    ull d; asm("fma.rn.f32x2 %0, %1, %2, %3;" : "=l"(d) : "l"(a), "l"(b), "l"(c)); return d;
}
__device__ __forceinline__ void upk2(ull v, float& lo, float& hi) {
    asm("mov.b64 {%0, %1}, %2;" : "=f"(lo), "=f"(hi) : "l"(v));
}

// 4x4 micro-tile step, rows packed in pairs, cols duplicated
__device__ __forceinline__ void micro_fma2(ull acc2[2][4], float4 a, float4 bb) {
    ull pa0 = pk2(a.x, a.y);
    ull pa1 = pk2(a.z, a.w);
    ull pb0 = pk2(bb.x, bb.x);
    ull pb1 = pk2(bb.y, bb.y);
    ull pb2 = pk2(bb.z, bb.z);
    ull pb3 = pk2(bb.w, bb.w);
    acc2[0][0] = fma2(pa0, pb0, acc2[0][0]);
    acc2[0][1] = fma2(pa0, pb1, acc2[0][1]);
    acc2[0][2] = fma2(pa0, pb2, acc2[0][2]);
    acc2[0][3] = fma2(pa0, pb3, acc2[0][3]);
    acc2[1][0] = fma2(pa1, pb0, acc2[1][0]);
    acc2[1][1] = fma2(pa1, pb1, acc2[1][1]);
    acc2[1][2] = fma2(pa1, pb2, acc2[1][2]);
    acc2[1][3] = fma2(pa1, pb3, acc2[1][3]);
}

// ---------------------------------------------------------------------------
// Per-batch fused GEMM (R5 body, batch as parameter). Grid (12,4).
// blockIdx.x < 8  -> WeT ; >= 8 -> Uh
// No data dependency on predecessors: no grid-dep sync needed.
// ---------------------------------------------------------------------------
__global__ __launch_bounds__(256) void gemm_b(const float* __restrict__ enc,
                                              const float* __restrict__ dec,
                                              const float* __restrict__ W,
                                              const float* __restrict__ U,
                                              int b) {
    cudaTriggerProgrammaticLaunchCompletion();   // let successor launch now

    __shared__ float As[2][16][64];
    __shared__ float Bs[2][16][68];

    int t = threadIdx.x;
    int tx = t & 15;
    int ty = t >> 4;

    ull acc2[2][4];
#pragma unroll
    for (int rp = 0; rp < 2; rp++)
#pragma unroll
        for (int c = 0; c < 4; c++) acc2[rp][c] = 0ull;

    bool weT = (blockIdx.x < 8);
    const float* Wm  = weT ? W : U;
    const float* act = weT ? (enc + (size_t)b * TE * H) : (dec + (size_t)b * TD * H);
    int h0 = blockIdx.y * 64;
    int c0 = weT ? blockIdx.x * 64 : (blockIdx.x - 8) * 64;

    int ka = t >> 4, hq = t & 15;
    int cc = t >> 2, kq = t & 3;

    {
        float4 aReg = *(const float4*)&Wm[ka * H + h0 + hq * 4];
        float4 bReg = *(const float4*)&act[(c0 + cc) * H + kq * 4];
        *(float4*)&As[0][ka][hq * 4] = aReg;
        Bs[0][kq * 4 + 0][cc] = bReg.x;
        Bs[0][kq * 4 + 1][cc] = bReg.y;
        Bs[0][kq * 4 + 2][cc] = bReg.z;
        Bs[0][kq * 4 + 3][cc] = bReg.w;
    }
    __syncthreads();

    if (weT) {
#pragma unroll 1
        for (int kt = 0; kt < 16; kt++) {
            int cur = kt & 1;
            float4 aReg, bReg;
            if (kt < 15) {
                int k0 = (kt + 1) * 16;
                aReg = *(const float4*)&Wm[(k0 + ka) * H + h0 + hq * 4];
                bReg = *(const float4*)&act[(c0 + cc) * H + k0 + kq * 4];
            }
#pragma unroll
            for (int kk = 0; kk < 16; kk++) {
                float4 a  = *(float4*)&As[cur][kk][ty * 4];
                float4 bb = *(float4*)&Bs[cur][kk][tx * 4];
                micro_fma2(acc2, a, bb);
            }
            if (kt < 15) {
                int nxt = cur ^ 1;
                *(float4*)&As[nxt][ka][hq * 4] = aReg;
                Bs[nxt][kq * 4 + 0][cc] = bReg.x;
                Bs[nxt][kq * 4 + 1][cc] = bReg.y;
                Bs[nxt][kq * 4 + 2][cc] = bReg.z;
                Bs[nxt][kq * 4 + 3][cc] = bReg.w;
                __syncthreads();
            }
        }
        float o[4][4];
#pragma unroll
        for (int rp = 0; rp < 2; rp++)
#pragma unroll
            for (int c = 0; c < 4; c++)
                upk2(acc2[rp][c], o[2 * rp][c], o[2 * rp + 1][c]);
        float* out = g_WeT + (size_t)b * H * TE;
#pragma unroll
        for (int r = 0; r < 4; r++) {
            float4 v = make_float4(o[r][0], o[r][1], o[r][2], o[r][3]);
            *(float4*)&out[(h0 + ty * 4 + r) * TE + c0 + tx * 4] = v;
        }
    } else {
#pragma unroll 1
        for (int kt = 0; kt < 16; kt++) {
            int cur = kt & 1;
            float4 aReg, bReg;
            if (kt < 15) {
                int k0 = (kt + 1) * 16;
                aReg = *(const float4*)&Wm[(k0 + ka) * H + h0 + hq * 4];
                bReg = *(const float4*)&act[(c0 + cc) * H + k0 + kq * 4];
            }
#pragma unroll
            for (int kk = 0; kk < 16; kk++) {
                float4 a  = *(float4*)&Bs[cur][kk][ty * 4];
                float4 bb = *(float4*)&As[cur][kk][tx * 4];
                micro_fma2(acc2, a, bb);
            }
            if (kt < 15) {
                int nxt = cur ^ 1;
                *(float4*)&As[nxt][ka][hq * 4] = aReg;
                Bs[nxt][kq * 4 + 0][cc] = bReg.x;
                Bs[nxt][kq * 4 + 1][cc] = bReg.y;
                Bs[nxt][kq * 4 + 2][cc] = bReg.z;
                Bs[nxt][kq * 4 + 3][cc] = bReg.w;
                __syncthreads();
            }
        }
        float o[4][4];
#pragma unroll
        for (int rp = 0; rp < 2; rp++)
#pragma unroll
            for (int c = 0; c < 4; c++)
                upk2(acc2[rp][c], o[2 * rp][c], o[2 * rp + 1][c]);
        float* out = g_Uh + (size_t)b * TD * H;
#pragma unroll
        for (int r = 0; r < 4; r++) {
            float4 v = make_float4(o[r][0], o[r][1], o[r][2], o[r][3]);
            *(float4*)&out[(c0 + ty * 4 + r) * H + h0 + tx * 4] = v;
        }
    }
}

// ---------------------------------------------------------------------------
// Per-batch energy + softmax (R5 body). Grid 64 blocks (JT=4), 512 threads.
// Depends on gemm_b (same batch): grid-dep sync before reading g_WeT/g_Uh.
// ---------------------------------------------------------------------------
__global__ __launch_bounds__(512) void energy_b(const float* __restrict__ Va,
                                                float* __restrict__ e_out,
                                                int b) {
    cudaTriggerProgrammaticLaunchCompletion();   // successor may launch
    cudaGridDependencySynchronize();             // wait gemm_b data

    __shared__ float Us4[H * 4];     // [h][jj]
    __shared__ float Vs[H];
    __shared__ float red[16][4];
    __shared__ float binv[4];

    int t  = threadIdx.x;
    int j0 = blockIdx.x * 4;

    for (int idx = t; idx < 4 * H; idx += 512) {
        int jj = idx >> 8;
        int h  = idx & (H - 1);
        Us4[h * 4 + jj] = g_Uh[((size_t)b * TD + j0 + jj) * H + h];
    }
    if (t < H) Vs[t] = Va[t];
    __syncthreads();

    const int i = t;
    const float* wp = g_WeT + (size_t)b * H * TE + i;

    float acc0 = 0.f, acc1 = 0.f, acc2 = 0.f, acc3 = 0.f;
#pragma unroll 4
    for (int h = 0; h < H; h++) {
        float w = wp[h * TE];
        float4 u = *(const float4*)&Us4[h * 4];
        float v = Vs[h];
        acc0 = fmaf(v, tanh_fast(w + u.x), acc0);
        acc1 = fmaf(v, tanh_fast(w + u.y), acc1);
        acc2 = fmaf(v, tanh_fast(w + u.z), acc2);
        acc3 = fmaf(v, tanh_fast(w + u.w), acc3);
    }

    // softmax over i (no max subtraction; |energy| <= sum|V| <= ~13)
    float p0 = __expf(acc0);
    float p1 = __expf(acc1);
    float p2 = __expf(acc2);
    float p3 = __expf(acc3);

    int lane = t & 31, wrp = t >> 5;
    float s0 = p0, s1 = p1, s2 = p2, s3 = p3;
#pragma unroll
    for (int o = 16; o; o >>= 1) {
        s0 += __shfl_xor_sync(0xffffffffu, s0, o);
        s1 += __shfl_xor_sync(0xffffffffu, s1, o);
        s2 += __shfl_xor_sync(0xffffffffu, s2, o);
        s3 += __shfl_xor_sync(0xffffffffu, s3, o);
    }
    if (lane == 0) { red[wrp][0] = s0; red[wrp][1] = s1; red[wrp][2] = s2; red[wrp][3] = s3; }
    __syncthreads();
    if (t < 4) {
        float s = 0.f;
#pragma unroll
        for (int w2 = 0; w2 < 16; w2++) s += red[w2][t];
        binv[t] = 1.0f / s;
    }
    __syncthreads();

    float* e0 = e_out + ((size_t)b * TD + j0) * TE;
    e0[0 * TE + i] = p0 * binv[0];
    e0[1 * TE + i] = p1 * binv[1];
    e0[2 * TE + i] = p2 * binv[2];
    e0[3 * TE + i] = p3 * binv[3];
}

// ---------------------------------------------------------------------------
// Per-batch context GEMM (R5 body). Grid (4,4), 256 threads.
// Depends on energy_b (same batch): grid-dep sync before reading e_out.
// ---------------------------------------------------------------------------
__global__ __launch_bounds__(256) void ctx_b(const float* __restrict__ P,
                                             const float* __restrict__ enc,
                                             float* __restrict__ c_out,
                                             int b) {
    cudaTriggerProgrammaticLaunchCompletion();   // successor may launch
    cudaGridDependencySynchronize();             // wait energy_b data

    __shared__ float As[2][16][68];
    __shared__ float Bs[2][16][64];

    int j0 = blockIdx.y * 64;
    int h0 = blockIdx.x * 64;
    int t  = threadIdx.x;
    int tx = t & 15;
    int ty = t >> 4;

    ull acc2[2][4];
#pragma unroll
    for (int rp = 0; rp < 2; rp++)
#pragma unroll
        for (int c = 0; c < 4; c++) acc2[rp][c] = 0ull;

    const float* Pb = P   + (size_t)b * TD * TE;
    const float* eb = enc + (size_t)b * TE * H;

    int jj = t >> 2, kq = t & 3;
    int kb = t >> 4, hq = t & 15;

    {
        float4 aReg = *(const float4*)&Pb[(j0 + jj) * TE + kq * 4];
        float4 bReg = *(const float4*)&eb[kb * H + h0 + hq * 4];
        As[0][kq * 4 + 0][jj] = aReg.x;
        As[0][kq * 4 + 1][jj] = aReg.y;
        As[0][kq * 4 + 2][jj] = aReg.z;
        As[0][kq * 4 + 3][jj] = aReg.w;
        *(float4*)&Bs[0][kb][hq * 4] = bReg;
    }
    __syncthreads();

#pragma unroll 1
    for (int kt = 0; kt < 32; kt++) {
        int cur = kt & 1;
        float4 aReg, bReg;
        if (kt < 31) {
            int k0 = (kt + 1) * 16;
            aReg = *(const float4*)&Pb[(j0 + jj) * TE + k0 + kq * 4];
            bReg = *(const float4*)&eb[(k0 + kb) * H + h0 + hq * 4];
        }
#pragma unroll
        for (int kk = 0; kk < 16; kk++) {
            float4 a  = *(float4*)&As[cur][kk][ty * 4];
            float4 bb = *(float4*)&Bs[cur][kk][tx * 4];
            micro_fma2(acc2, a, bb);
        }
        if (kt < 31) {
            int nxt = cur ^ 1;
            As[nxt][kq * 4 + 0][jj] = aReg.x;
            As[nxt][kq * 4 + 1][jj] = aReg.y;
            As[nxt][kq * 4 + 2][jj] = aReg.z;
            As[nxt][kq * 4 + 3][jj] = aReg.w;
            *(float4*)&Bs[nxt][kb][hq * 4] = bReg;
            __syncthreads();
        }
    }

    float o[4][4];
#pragma unroll
    for (int rp = 0; rp < 2; rp++)
#pragma unroll
        for (int c = 0; c < 4; c++)
            upk2(acc2[rp][c], o[2 * rp][c], o[2 * rp + 1][c]);

#pragma unroll
    for (int r = 0; r < 4; r++) {
        float4 v = make_float4(o[r][0], o[r][1], o[r][2], o[r][3]);
        *(float4*)&c_out[((size_t)b * TD + j0 + ty * 4 + r) * H + h0 + tx * 4] = v;
    }
}

// ---------------------------------------------------------------------------
// PDL launch chain: g0,e0,c0,g1,e1,c1,... — every kernel triggers launch
// completion immediately; data deps enforced by cudaGridDependencySynchronize.
// ---------------------------------------------------------------------------
extern "C" void kernel_launch(void* const* d_in, const int* in_sizes, int n_in,
                              void* d_out, int out_size) {
    const float* enc = (const float*)d_in[0];  // [B,TE,H]
    const float* dec = (const float*)d_in[1];  // [B,TD,H]
    const float* W   = (const float*)d_in[2];  // [H,H]
    const float* U   = (const float*)d_in[3];  // [H,H]
    const float* V   = (const float*)d_in[4];  // [H,1]

    float* c_out = (float*)d_out;              // [B,TD,H]
    float* e_out = (float*)d_out + B * TD * H; // [B,TD,TE]

    cudaLaunchAttribute pdl;
    pdl.id = cudaLaunchAttributeProgrammaticStreamSerialization;
    pdl.val.programmaticStreamSerializationAllowed = 1;

    for (int b = 0; b < B; b++) {
        {
            cudaLaunchConfig_t cfg = {};
            cfg.gridDim = dim3(12, 4, 1);
            cfg.blockDim = dim3(256, 1, 1);
            cfg.stream = 0;
            cfg.attrs = &pdl;
            cfg.numAttrs = 1;
            cudaLaunchKernelEx(&cfg, gemm_b, enc, dec, W, U, b);
        }
        {
            cudaLaunchConfig_t cfg = {};
            cfg.gridDim = dim3(TD / 4, 1, 1);      // 64 blocks
            cfg.blockDim = dim3(512, 1, 1);
            cfg.stream = 0;
            cfg.attrs = &pdl;
            cfg.numAttrs = 1;
            cudaLaunchKernelEx(&cfg, energy_b, (const float*)V, (float*)e_out, b);
        }
        {
            cudaLaunchConfig_t cfg = {};
            cfg.gridDim = dim3(H / 64, TD / 64, 1); // (4,4)
            cfg.blockDim = dim3(256, 1, 1);
            cfg.stream = 0;
            cfg.attrs = &pdl;
            cfg.numAttrs = 1;
            cudaLaunchKernelEx(&cfg, ctx_b, (const float*)e_out, enc, (float*)c_out, b);
        }
    }
}

// round 13
// speedup vs baseline: 2.4069x; 2.4069x over previous
#include <cuda_runtime.h>
#include <cstdint>

#define B 8
#define TE 512
#define TD 256
#define H 256

#define NBLK 592           // ~4 blocks/SM on 148 SMs
#define N_GEMM_PER_B 48    // 32 WeT tiles + 16 Uh tiles
#define N_ENER_PER_B 64    // TD/4 units of 4 decoder rows
#define ITEMS_PER_B (N_GEMM_PER_B + N_ENER_PER_B)   // 112
#define N_CTX 128          // 8 batches * (4x4) tiles
#define TOTAL (B * ITEMS_PER_B + N_CTX)             // 1024

typedef unsigned long long ull;

// Scratch + sync state (device globals: no allocations allowed)
__device__ float g_WeT[B * H * TE];  // [b][h][i]
__device__ float g_Uh [B * TD * H];  // [b][j][h]
__device__ int   g_q;                // work-queue head
__device__ int   g_done[B];          // gemm tiles finished per batch (target 48)
__device__ int   g_edone[B];         // energy units finished per batch (target 64)

__device__ __forceinline__ float tanh_fast(float x) {
    float y;
    asm("tanh.approx.f32 %0, %1;" : "=f"(y) : "f"(x));
    return y;
}

// ---- packed fp32x2 helpers ----
__device__ __forceinline__ ull pk2(float lo, float hi) {
    ull r; asm("mov.b64 %0, {%1, %2};" : "=l"(r) : "f"(lo), "f"(hi)); return r;
}
__device__ __forceinline__ ull fma2(ull a, ull b, ull c) {
    ull d; asm("fma.rn.f32x2 %0, %1, %2, %3;" : "=l"(d) : "l"(a), "l"(b), "l"(c)); return d;
}
__device__ __forceinline__ void upk2(ull v, float& lo, float& hi) {
    asm("mov.b64 {%0, %1}, %2;" : "=f"(lo), "=f"(hi) : "l"(v));
}

__device__ __forceinline__ void micro_fma2(ull acc2[2][4], float4 a, float4 bb) {
    ull pa0 = pk2(a.x, a.y);
    ull pa1 = pk2(a.z, a.w);
    ull pb0 = pk2(bb.x, bb.x);
    ull pb1 = pk2(bb.y, bb.y);
    ull pb2 = pk2(bb.z, bb.z);
    ull pb3 = pk2(bb.w, bb.w);
    acc2[0][0] = fma2(pa0, pb0, acc2[0][0]);
    acc2[0][1] = fma2(pa0, pb1, acc2[0][1]);
    acc2[0][2] = fma2(pa0, pb2, acc2[0][2]);
    acc2[0][3] = fma2(pa0, pb3, acc2[0][3]);
    acc2[1][0] = fma2(pa1, pb0, acc2[1][0]);
    acc2[1][1] = fma2(pa1, pb1, acc2[1][1]);
    acc2[1][2] = fma2(pa1, pb2, acc2[1][2]);
    acc2[1][3] = fma2(pa1, pb3, acc2[1][3]);
}

// ===========================================================================
// Work-item bodies (256 threads each). smem passed as raw byte array.
// ===========================================================================

// ---- GEMM tile (R5 body): weT? WeT[b][h0:+64][i0:+64] : Uh[b][j0:+64][h0:+64]
__device__ __forceinline__ void gemm_tile(char* sm, const float* __restrict__ enc,
                                          const float* __restrict__ dec,
                                          const float* __restrict__ W,
                                          const float* __restrict__ U,
                                          int b, int c0, int h0, bool weT) {
    float (*As)[64] = (float(*)[64])sm;              // [2*16][64]  8 KB
    float (*Bs)[68] = (float(*)[68])(sm + 8192);     // [2*16][68]  8.5 KB

    int t = threadIdx.x;
    int tx = t & 15;
    int ty = t >> 4;

    ull acc2[2][4];
#pragma unroll
    for (int rp = 0; rp < 2; rp++)
#pragma unroll
        for (int c = 0; c < 4; c++) acc2[rp][c] = 0ull;

    const float* Wm  = weT ? W : U;
    const float* act = weT ? (enc + (size_t)b * TE * H) : (dec + (size_t)b * TD * H);

    int ka = t >> 4, hq = t & 15;
    int cc = t >> 2, kq = t & 3;

    {
        float4 aReg = *(const float4*)&Wm[ka * H + h0 + hq * 4];
        float4 bReg = *(const float4*)&act[(c0 + cc) * H + kq * 4];
        *(float4*)&As[0 * 16 + ka][hq * 4] = aReg;
        Bs[0 * 16 + kq * 4 + 0][cc] = bReg.x;
        Bs[0 * 16 + kq * 4 + 1][cc] = bReg.y;
        Bs[0 * 16 + kq * 4 + 2][cc] = bReg.z;
        Bs[0 * 16 + kq * 4 + 3][cc] = bReg.w;
    }
    __syncthreads();

#pragma unroll 1
    for (int kt = 0; kt < 16; kt++) {
        int cur = (kt & 1) * 16;
        float4 aReg, bReg;
        if (kt < 15) {
            int k0 = (kt + 1) * 16;
            aReg = *(const float4*)&Wm[(k0 + ka) * H + h0 + hq * 4];
            bReg = *(const float4*)&act[(c0 + cc) * H + k0 + kq * 4];
        }
        if (weT) {
#pragma unroll
            for (int kk = 0; kk < 16; kk++) {
                float4 a  = *(float4*)&As[cur + kk][ty * 4];
                float4 bb = *(float4*)&Bs[cur + kk][tx * 4];
                micro_fma2(acc2, a, bb);
            }
        } else {
#pragma unroll
            for (int kk = 0; kk < 16; kk++) {
                float4 a  = *(float4*)&Bs[cur + kk][ty * 4];
                float4 bb = *(float4*)&As[cur + kk][tx * 4];
                micro_fma2(acc2, a, bb);
            }
        }
        if (kt < 15) {
            int nxt = ((kt + 1) & 1) * 16;
            *(float4*)&As[nxt + ka][hq * 4] = aReg;
            Bs[nxt + kq * 4 + 0][cc] = bReg.x;
            Bs[nxt + kq * 4 + 1][cc] = bReg.y;
            Bs[nxt + kq * 4 + 2][cc] = bReg.z;
            Bs[nxt + kq * 4 + 3][cc] = bReg.w;
            __syncthreads();
        }
    }

    float o[4][4];
#pragma unroll
    for (int rp = 0; rp < 2; rp++)
#pragma unroll
        for (int c = 0; c < 4; c++)
            upk2(acc2[rp][c], o[2 * rp][c], o[2 * rp + 1][c]);

    if (weT) {
        float* out = g_WeT + (size_t)b * H * TE;
#pragma unroll
        for (int r = 0; r < 4; r++) {
            float4 v = make_float4(o[r][0], o[r][1], o[r][2], o[r][3]);
            *(float4*)&out[(h0 + ty * 4 + r) * TE + c0 + tx * 4] = v;
        }
    } else {
        float* out = g_Uh + (size_t)b * TD * H;
#pragma unroll
        for (int r = 0; r < 4; r++) {
            float4 v = make_float4(o[r][0], o[r][1], o[r][2], o[r][3]);
            *(float4*)&out[(c0 + ty * 4 + r) * H + h0 + tx * 4] = v;
        }
    }
}

// ---- Energy unit: 4 decoder rows, 256 threads, 2 i-values per thread ----
__device__ __forceinline__ void energy_unit(char* sm, const float* __restrict__ Va,
                                            float* __restrict__ e_out,
                                            int b, int j0) {
    float* Us4 = (float*)sm;               // [H][4]  4 KB
    float* Vs  = (float*)(sm + 4096);      // [H]     1 KB
    float (*red)[4] = (float(*)[4])(sm + 5120);  // [8][4]
    float* binv = (float*)(sm + 5248);     // [4]

    int t = threadIdx.x;

    for (int idx = t; idx < 4 * H; idx += 256) {
        int jj = idx >> 8;
        int h  = idx & (H - 1);
        Us4[h * 4 + jj] = g_Uh[((size_t)b * TD + j0 + jj) * H + h];
    }
    Vs[t] = Va[t];                          // H == 256 == blockDim
    __syncthreads();

    const float* wp = g_WeT + (size_t)b * H * TE;

    float aA[4] = {0.f, 0.f, 0.f, 0.f};     // i = t
    float aB[4] = {0.f, 0.f, 0.f, 0.f};     // i = t + 256
#pragma unroll 4
    for (int h = 0; h < H; h++) {
        float w0 = wp[h * TE + t];
        float w1 = wp[h * TE + t + 256];
        float4 u = *(const float4*)&Us4[h * 4];
        float v = Vs[h];
        aA[0] = fmaf(v, tanh_fast(w0 + u.x), aA[0]);
        aA[1] = fmaf(v, tanh_fast(w0 + u.y), aA[1]);
        aA[2] = fmaf(v, tanh_fast(w0 + u.z), aA[2]);
        aA[3] = fmaf(v, tanh_fast(w0 + u.w), aA[3]);
        aB[0] = fmaf(v, tanh_fast(w1 + u.x), aB[0]);
        aB[1] = fmaf(v, tanh_fast(w1 + u.y), aB[1]);
        aB[2] = fmaf(v, tanh_fast(w1 + u.z), aB[2]);
        aB[3] = fmaf(v, tanh_fast(w1 + u.w), aB[3]);
    }

    // softmax over i (no max subtraction: |energy| <= sum|V| <= ~13)
    float pA[4], pB[4], s[4];
#pragma unroll
    for (int k = 0; k < 4; k++) {
        pA[k] = __expf(aA[k]);
        pB[k] = __expf(aB[k]);
        s[k] = pA[k] + pB[k];
    }
    int lane = t & 31, wrp = t >> 5;
#pragma unroll
    for (int o = 16; o; o >>= 1) {
#pragma unroll
        for (int k = 0; k < 4; k++) s[k] += __shfl_xor_sync(0xffffffffu, s[k], o);
    }
    if (lane == 0) {
#pragma unroll
        for (int k = 0; k < 4; k++) red[wrp][k] = s[k];
    }
    __syncthreads();
    if (t < 4) {
        float acc = 0.f;
#pragma unroll
        for (int w2 = 0; w2 < 8; w2++) acc += red[w2][t];
        binv[t] = 1.0f / acc;
    }
    __syncthreads();

    float* e0 = e_out + ((size_t)b * TD + j0) * TE;
#pragma unroll
    for (int k = 0; k < 4; k++) {
        float bv = binv[k];
        e0[k * TE + t]       = pA[k] * bv;
        e0[k * TE + t + 256] = pB[k] * bv;
    }
}

// ---- Context tile (R5 body): c[b][j0:+64][h0:+64] = P @ enc ----
__device__ __forceinline__ void ctx_tile(char* sm, const float* __restrict__ P,
                                         const float* __restrict__ enc,
                                         float* __restrict__ c_out,
                                         int b, int j0, int h0) {
    float (*As)[68] = (float(*)[68])sm;              // [2*16][68]  8.5 KB
    float (*Bs)[64] = (float(*)[64])(sm + 8704);     // [2*16][64]  8 KB

    int t  = threadIdx.x;
    int tx = t & 15;
    int ty = t >> 4;

    ull acc2[2][4];
#pragma unroll
    for (int rp = 0; rp < 2; rp++)
#pragma unroll
        for (int c = 0; c < 4; c++) acc2[rp][c] = 0ull;

    const float* Pb = P   + (size_t)b * TD * TE;
    const float* eb = enc + (size_t)b * TE * H;

    int jj = t >> 2, kq = t & 3;
    int kb = t >> 4, hq = t & 15;

    {
        float4 aReg = *(const float4*)&Pb[(j0 + jj) * TE + kq * 4];
        float4 bReg = *(const float4*)&eb[kb * H + h0 + hq * 4];
        As[0 * 16 + kq * 4 + 0][jj] = aReg.x;
        As[0 * 16 + kq * 4 + 1][jj] = aReg.y;
        As[0 * 16 + kq * 4 + 2][jj] = aReg.z;
        As[0 * 16 + kq * 4 + 3][jj] = aReg.w;
        *(float4*)&Bs[0 * 16 + kb][hq * 4] = bReg;
    }
    __syncthreads();

#pragma unroll 1
    for (int kt = 0; kt < 32; kt++) {
        int cur = (kt & 1) * 16;
        float4 aReg, bReg;
        if (kt < 31) {
            int k0 = (kt + 1) * 16;
            aReg = *(const float4*)&Pb[(j0 + jj) * TE + k0 + kq * 4];
            bReg = *(const float4*)&eb[(k0 + kb) * H + h0 + hq * 4];
        }
#pragma unroll
        for (int kk = 0; kk < 16; kk++) {
            float4 a  = *(float4*)&As[cur + kk][ty * 4];
            float4 bb = *(float4*)&Bs[cur + kk][tx * 4];
            micro_fma2(acc2, a, bb);
        }
        if (kt < 31) {
            int nxt = ((kt + 1) & 1) * 16;
            As[nxt + kq * 4 + 0][jj] = aReg.x;
            As[nxt + kq * 4 + 1][jj] = aReg.y;
            As[nxt + kq * 4 + 2][jj] = aReg.z;
            As[nxt + kq * 4 + 3][jj] = aReg.w;
            *(float4*)&Bs[nxt + kb][hq * 4] = bReg;
            __syncthreads();
        }
    }

    float o[4][4];
#pragma unroll
    for (int rp = 0; rp < 2; rp++)
#pragma unroll
        for (int c = 0; c < 4; c++)
            upk2(acc2[rp][c], o[2 * rp][c], o[2 * rp + 1][c]);

#pragma unroll
    for (int r = 0; r < 4; r++) {
        float4 v = make_float4(o[r][0], o[r][1], o[r][2], o[r][3]);
        *(float4*)&c_out[((size_t)b * TD + j0 + ty * 4 + r) * H + h0 + tx * 4] = v;
    }
}

// ===========================================================================
// Init: reset queue + flags (runs before main kernel every launch/replay)
// ===========================================================================
__global__ void init_kernel() {
    int t = threadIdx.x;
    if (t == 0) g_q = 0;
    if (t < B) { g_done[t] = 0; g_edone[t] = 0; }
}

// ===========================================================================
// Persistent uber-kernel: work queue of 1024 items.
// Per batch b: items [b*112, b*112+48) = gemm tiles, [+48, +112) = energy.
// Items [896, 1024) = ctx tiles.
// ===========================================================================
__global__ __launch_bounds__(256) void uber_kernel(const float* __restrict__ enc,
                                                   const float* __restrict__ dec,
                                                   const float* __restrict__ W,
                                                   const float* __restrict__ U,
                                                   const float* __restrict__ Va,
                                                   float* __restrict__ c_out,
                                                   float* __restrict__ e_out) {
    __shared__ char sm_raw[17408];
    __shared__ int s_item;

    int t = threadIdx.x;

    while (true) {
        __syncthreads();                      // quiesce smem/s_item from prev item
        if (t == 0) s_item = atomicAdd(&g_q, 1);
        __syncthreads();
        int item = s_item;
        if (item >= TOTAL) break;

        if (item < B * ITEMS_PER_B) {
            int b = item / ITEMS_PER_B;
            int r = item % ITEMS_PER_B;
            if (r < N_GEMM_PER_B) {
                // ---- gemm tile ----
                int c0, h0;
                bool weT;
                if (r < 32) { weT = true;  c0 = (r & 7) * 64;        h0 = (r >> 3) * 64; }
                else        { weT = false; c0 = ((r - 32) & 3) * 64; h0 = ((r - 32) >> 2) * 64; }
                gemm_tile(sm_raw, enc, dec, W, U, b, c0, h0, weT);
                __threadfence();              // release: stores visible before flag
                __syncthreads();
                if (t == 0) atomicAdd(&g_done[b], 1);
            } else {
                // ---- energy unit (waits for batch's gemm) ----
                int j0 = (r - N_GEMM_PER_B) * 4;
                if (t == 0) {
                    while (atomicAdd(&g_done[b], 0) < N_GEMM_PER_B) __nanosleep(64);
                    __threadfence();          // acquire
                }
                __syncthreads();
                energy_unit(sm_raw, Va, e_out, b, j0);
                __threadfence();
                __syncthreads();
                if (t == 0) atomicAdd(&g_edone[b], 1);
            }
        } else {
            // ---- ctx tile (waits for batch's energy) ----
            int v = item - B * ITEMS_PER_B;
            int b = v >> 4;
            int s = v & 15;
            int j0 = (s >> 2) * 64;
            int h0 = (s & 3) * 64;
            if (t == 0) {
                while (atomicAdd(&g_edone[b], 0) < N_ENER_PER_B) __nanosleep(64);
                __threadfence();              // acquire
            }
            __syncthreads();
            ctx_tile(sm_raw, e_out, enc, c_out, b, j0, h0);
        }
    }
}

// ---------------------------------------------------------------------------
extern "C" void kernel_launch(void* const* d_in, const int* in_sizes, int n_in,
                              void* d_out, int out_size) {
    const float* enc = (const float*)d_in[0];  // [B,TE,H]
    const float* dec = (const float*)d_in[1];  // [B,TD,H]
    const float* W   = (const float*)d_in[2];  // [H,H]
    const float* U   = (const float*)d_in[3];  // [H,H]
    const float* V   = (const float*)d_in[4];  // [H,1]

    float* c_out = (float*)d_out;              // [B,TD,H]
    float* e_out = (float*)d_out + B * TD * H; // [B,TD,TE]

    init_kernel<<<1, 32>>>();
    uber_kernel<<<NBLK, 256>>>(enc, dec, W, U, V, c_out, e_out);
}

// round 14
// speedup vs baseline: 2.8808x; 1.1969x over previous
#include <cuda_runtime.h>
#include <cstdint>

#define B 8
#define TE 512
#define TD 256
#define H 256

#define N_GEMM 384          // 8 batches * 48 tiles (32 WeT + 16 Uh)
#define N_ENER 512          // 8 batches * 64 units (4 rows each)
#define N_CTX  128          // 8 batches * 16 tiles
#define NBLK (N_GEMM + N_ENER + N_CTX)   // 1024

typedef unsigned long long ull;

// Scratch + sync state (device globals: no allocations allowed)
__device__ float g_WeT[B * H * TE];  // [b][h][i]
__device__ float g_Uh [B * TD * H];  // [b][j][h]
__device__ int   g_done[B];          // gemm tiles finished per batch (target 48)
__device__ int   g_edone[B];         // energy units finished per batch (target 64)

__device__ __forceinline__ float tanh_fast(float x) {
    float y;
    asm("tanh.approx.f32 %0, %1;" : "=f"(y) : "f"(x));
    return y;
}

// ---- packed fp32x2 helpers ----
__device__ __forceinline__ ull pk2(float lo, float hi) {
    ull r; asm("mov.b64 %0, {%1, %2};" : "=l"(r) : "f"(lo), "f"(hi)); return r;
}
__device__ __forceinline__ ull fma2(ull a, ull b, ull c) {
    ull d; asm("fma.rn.f32x2 %0, %1, %2, %3;" : "=l"(d) : "l"(a), "l"(b), "l"(c)); return d;
}
__device__ __forceinline__ void upk2(ull v, float& lo, float& hi) {
    asm("mov.b64 {%0, %1}, %2;" : "=f"(lo), "=f"(hi) : "l"(v));
}

__device__ __forceinline__ void micro_fma2(ull acc2[2][4], float4 a, float4 bb) {
    ull pa0 = pk2(a.x, a.y);
    ull pa1 = pk2(a.z, a.w);
    ull pb0 = pk2(bb.x, bb.x);
    ull pb1 = pk2(bb.y, bb.y);
    ull pb2 = pk2(bb.z, bb.z);
    ull pb3 = pk2(bb.w, bb.w);
    acc2[0][0] = fma2(pa0, pb0, acc2[0][0]);
    acc2[0][1] = fma2(pa0, pb1, acc2[0][1]);
    acc2[0][2] = fma2(pa0, pb2, acc2[0][2]);
    acc2[0][3] = fma2(pa0, pb3, acc2[0][3]);
    acc2[1][0] = fma2(pa1, pb0, acc2[1][0]);
    acc2[1][1] = fma2(pa1, pb1, acc2[1][1]);
    acc2[1][2] = fma2(pa1, pb2, acc2[1][2]);
    acc2[1][3] = fma2(pa1, pb3, acc2[1][3]);
}

// ===========================================================================
// Work-item bodies (verbatim from R13, which passed correctness)
// ===========================================================================

__device__ __forceinline__ void gemm_tile(char* sm, const float* __restrict__ enc,
                                          const float* __restrict__ dec,
                                          const float* __restrict__ W,
                                          const float* __restrict__ U,
                                          int b, int c0, int h0, bool weT) {
    float (*As)[64] = (float(*)[64])sm;              // [2*16][64]
    float (*Bs)[68] = (float(*)[68])(sm + 8192);     // [2*16][68]

    int t = threadIdx.x;
    int tx = t & 15;
    int ty = t >> 4;

    ull acc2[2][4];
#pragma unroll
    for (int rp = 0; rp < 2; rp++)
#pragma unroll
        for (int c = 0; c < 4; c++) acc2[rp][c] = 0ull;

    const float* Wm  = weT ? W : U;
    const float* act = weT ? (enc + (size_t)b * TE * H) : (dec + (size_t)b * TD * H);

    int ka = t >> 4, hq = t & 15;
    int cc = t >> 2, kq = t & 3;

    {
        float4 aReg = *(const float4*)&Wm[ka * H + h0 + hq * 4];
        float4 bReg = *(const float4*)&act[(c0 + cc) * H + kq * 4];
        *(float4*)&As[0 * 16 + ka][hq * 4] = aReg;
        Bs[0 * 16 + kq * 4 + 0][cc] = bReg.x;
        Bs[0 * 16 + kq * 4 + 1][cc] = bReg.y;
        Bs[0 * 16 + kq * 4 + 2][cc] = bReg.z;
        Bs[0 * 16 + kq * 4 + 3][cc] = bReg.w;
    }
    __syncthreads();

#pragma unroll 1
    for (int kt = 0; kt < 16; kt++) {
        int cur = (kt & 1) * 16;
        float4 aReg, bReg;
        if (kt < 15) {
            int k0 = (kt + 1) * 16;
            aReg = *(const float4*)&Wm[(k0 + ka) * H + h0 + hq * 4];
            bReg = *(const float4*)&act[(c0 + cc) * H + k0 + kq * 4];
        }
        if (weT) {
#pragma unroll
            for (int kk = 0; kk < 16; kk++) {
                float4 a  = *(float4*)&As[cur + kk][ty * 4];
                float4 bb = *(float4*)&Bs[cur + kk][tx * 4];
                micro_fma2(acc2, a, bb);
            }
        } else {
#pragma unroll
            for (int kk = 0; kk < 16; kk++) {
                float4 a  = *(float4*)&Bs[cur + kk][ty * 4];
                float4 bb = *(float4*)&As[cur + kk][tx * 4];
                micro_fma2(acc2, a, bb);
            }
        }
        if (kt < 15) {
            int nxt = ((kt + 1) & 1) * 16;
            *(float4*)&As[nxt + ka][hq * 4] = aReg;
            Bs[nxt + kq * 4 + 0][cc] = bReg.x;
            Bs[nxt + kq * 4 + 1][cc] = bReg.y;
            Bs[nxt + kq * 4 + 2][cc] = bReg.z;
            Bs[nxt + kq * 4 + 3][cc] = bReg.w;
            __syncthreads();
        }
    }

    float o[4][4];
#pragma unroll
    for (int rp = 0; rp < 2; rp++)
#pragma unroll
        for (int c = 0; c < 4; c++)
            upk2(acc2[rp][c], o[2 * rp][c], o[2 * rp + 1][c]);

    if (weT) {
        float* out = g_WeT + (size_t)b * H * TE;
#pragma unroll
        for (int r = 0; r < 4; r++) {
            float4 v = make_float4(o[r][0], o[r][1], o[r][2], o[r][3]);
            *(float4*)&out[(h0 + ty * 4 + r) * TE + c0 + tx * 4] = v;
        }
    } else {
        float* out = g_Uh + (size_t)b * TD * H;
#pragma unroll
        for (int r = 0; r < 4; r++) {
            float4 v = make_float4(o[r][0], o[r][1], o[r][2], o[r][3]);
            *(float4*)&out[(c0 + ty * 4 + r) * H + h0 + tx * 4] = v;
        }
    }
}

__device__ __forceinline__ void energy_unit(char* sm, const float* __restrict__ Va,
                                            float* __restrict__ e_out,
                                            int b, int j0) {
    float* Us4 = (float*)sm;                     // [H][4]
    float* Vs  = (float*)(sm + 4096);            // [H]
    float (*red)[4] = (float(*)[4])(sm + 5120);  // [8][4]
    float* binv = (float*)(sm + 5248);           // [4]

    int t = threadIdx.x;

    for (int idx = t; idx < 4 * H; idx += 256) {
        int jj = idx >> 8;
        int h  = idx & (H - 1);
        Us4[h * 4 + jj] = g_Uh[((size_t)b * TD + j0 + jj) * H + h];
    }
    Vs[t] = Va[t];
    __syncthreads();

    const float* wp = g_WeT + (size_t)b * H * TE;

    float aA[4] = {0.f, 0.f, 0.f, 0.f};
    float aB[4] = {0.f, 0.f, 0.f, 0.f};
#pragma unroll 4
    for (int h = 0; h < H; h++) {
        float w0 = wp[h * TE + t];
        float w1 = wp[h * TE + t + 256];
        float4 u = *(const float4*)&Us4[h * 4];
        float v = Vs[h];
        aA[0] = fmaf(v, tanh_fast(w0 + u.x), aA[0]);
        aA[1] = fmaf(v, tanh_fast(w0 + u.y), aA[1]);
        aA[2] = fmaf(v, tanh_fast(w0 + u.z), aA[2]);
        aA[3] = fmaf(v, tanh_fast(w0 + u.w), aA[3]);
        aB[0] = fmaf(v, tanh_fast(w1 + u.x), aB[0]);
        aB[1] = fmaf(v, tanh_fast(w1 + u.y), aB[1]);
        aB[2] = fmaf(v, tanh_fast(w1 + u.z), aB[2]);
        aB[3] = fmaf(v, tanh_fast(w1 + u.w), aB[3]);
    }

    float pA[4], pB[4], s[4];
#pragma unroll
    for (int k = 0; k < 4; k++) {
        pA[k] = __expf(aA[k]);
        pB[k] = __expf(aB[k]);
        s[k] = pA[k] + pB[k];
    }
    int lane = t & 31, wrp = t >> 5;
#pragma unroll
    for (int o = 16; o; o >>= 1) {
#pragma unroll
        for (int k = 0; k < 4; k++) s[k] += __shfl_xor_sync(0xffffffffu, s[k], o);
    }
    if (lane == 0) {
#pragma unroll
        for (int k = 0; k < 4; k++) red[wrp][k] = s[k];
    }
    __syncthreads();
    if (t < 4) {
        float acc = 0.f;
#pragma unroll
        for (int w2 = 0; w2 < 8; w2++) acc += red[w2][t];
        binv[t] = 1.0f / acc;
    }
    __syncthreads();

    float* e0 = e_out + ((size_t)b * TD + j0) * TE;
#pragma unroll
    for (int k = 0; k < 4; k++) {
        float bv = binv[k];
        e0[k * TE + t]       = pA[k] * bv;
        e0[k * TE + t + 256] = pB[k] * bv;
    }
}

__device__ __forceinline__ void ctx_tile(char* sm, const float* __restrict__ P,
                                         const float* __restrict__ enc,
                                         float* __restrict__ c_out,
                                         int b, int j0, int h0) {
    float (*As)[68] = (float(*)[68])sm;              // [2*16][68]
    float (*Bs)[64] = (float(*)[64])(sm + 8704);     // [2*16][64]

    int t  = threadIdx.x;
    int tx = t & 15;
    int ty = t >> 4;

    ull acc2[2][4];
#pragma unroll
    for (int rp = 0; rp < 2; rp++)
#pragma unroll
        for (int c = 0; c < 4; c++) acc2[rp][c] = 0ull;

    const float* Pb = P   + (size_t)b * TD * TE;
    const float* eb = enc + (size_t)b * TE * H;

    int jj = t >> 2, kq = t & 3;
    int kb = t >> 4, hq = t & 15;

    {
        float4 aReg = *(const float4*)&Pb[(j0 + jj) * TE + kq * 4];
        float4 bReg = *(const float4*)&eb[kb * H + h0 + hq * 4];
        As[0 * 16 + kq * 4 + 0][jj] = aReg.x;
        As[0 * 16 + kq * 4 + 1][jj] = aReg.y;
        As[0 * 16 + kq * 4 + 2][jj] = aReg.z;
        As[0 * 16 + kq * 4 + 3][jj] = aReg.w;
        *(float4*)&Bs[0 * 16 + kb][hq * 4] = bReg;
    }
    __syncthreads();

#pragma unroll 1
    for (int kt = 0; kt < 32; kt++) {
        int cur = (kt & 1) * 16;
        float4 aReg, bReg;
        if (kt < 31) {
            int k0 = (kt + 1) * 16;
            aReg = *(const float4*)&Pb[(j0 + jj) * TE + k0 + kq * 4];
            bReg = *(const float4*)&eb[(k0 + kb) * H + h0 + hq * 4];
        }
#pragma unroll
        for (int kk = 0; kk < 16; kk++) {
            float4 a  = *(float4*)&As[cur + kk][ty * 4];
            float4 bb = *(float4*)&Bs[cur + kk][tx * 4];
            micro_fma2(acc2, a, bb);
        }
        if (kt < 31) {
            int nxt = ((kt + 1) & 1) * 16;
            As[nxt + kq * 4 + 0][jj] = aReg.x;
            As[nxt + kq * 4 + 1][jj] = aReg.y;
            As[nxt + kq * 4 + 2][jj] = aReg.z;
            As[nxt + kq * 4 + 3][jj] = aReg.w;
            *(float4*)&Bs[nxt + kb][hq * 4] = bReg;
            __syncthreads();
        }
    }

    float o[4][4];
#pragma unroll
    for (int rp = 0; rp < 2; rp++)
#pragma unroll
        for (int c = 0; c < 4; c++)
            upk2(acc2[rp][c], o[2 * rp][c], o[2 * rp + 1][c]);

#pragma unroll
    for (int r = 0; r < 4; r++) {
        float4 v = make_float4(o[r][0], o[r][1], o[r][2], o[r][3]);
        *(float4*)&c_out[((size_t)b * TD + j0 + ty * 4 + r) * H + h0 + tx * 4] = v;
    }
}

// ===========================================================================
// Init: reset flags (runs before main kernel every launch/replay)
// ===========================================================================
__global__ void init_kernel() {
    int t = threadIdx.x;
    if (t < B) { g_done[t] = 0; g_edone[t] = 0; }
}

// ===========================================================================
// Static-role kernel: 1024 blocks, one item each, in dispatch order:
//   [0,384)    gemm tiles   (batch-major; never wait)
//   [384,896)  energy units (wait g_done[b]==48)
//   [896,1024) ctx tiles    (wait g_edone[b]==64)
// ===========================================================================
__global__ __launch_bounds__(256) void attn_static(const float* __restrict__ enc,
                                                   const float* __restrict__ dec,
                                                   const float* __restrict__ W,
                                                   const float* __restrict__ U,
                                                   const float* __restrict__ Va,
                                                   float* __restrict__ c_out,
                                                   float* __restrict__ e_out) {
    __shared__ char sm_raw[17408];

    int t   = threadIdx.x;
    int blk = blockIdx.x;

    if (blk < N_GEMM) {
        // ---- gemm tile ----
        int b = blk / 48;
        int r = blk % 48;
        int c0, h0;
        bool weT;
        if (r < 32) { weT = true;  c0 = (r & 7) * 64;        h0 = (r >> 3) * 64; }
        else        { weT = false; c0 = ((r - 32) & 3) * 64; h0 = ((r - 32) >> 2) * 64; }
        gemm_tile(sm_raw, enc, dec, W, U, b, c0, h0, weT);
        __threadfence();                  // release: stores visible before flag
        __syncthreads();
        if (t == 0) atomicAdd(&g_done[b], 1);
    } else if (blk < N_GEMM + N_ENER) {
        // ---- energy unit ----
        int v = blk - N_GEMM;
        int b = v >> 6;                   // /64
        int j0 = (v & 63) * 4;
        if (t == 0) {
            while (atomicAdd(&g_done[b], 0) < 48) __nanosleep(128);
            __threadfence();              // acquire
        }
        __syncthreads();
        energy_unit(sm_raw, Va, e_out, b, j0);
        __threadfence();
        __syncthreads();
        if (t == 0) atomicAdd(&g_edone[b], 1);
    } else {
        // ---- ctx tile ----
        int v = blk - N_GEMM - N_ENER;
        int b = v >> 4;
        int s = v & 15;
        int j0 = (s >> 2) * 64;
        int h0 = (s & 3) * 64;
        if (t == 0) {
            while (atomicAdd(&g_edone[b], 0) < 64) __nanosleep(128);
            __threadfence();              // acquire
        }
        __syncthreads();
        ctx_tile(sm_raw, e_out, enc, c_out, b, j0, h0);
    }
}

// ---------------------------------------------------------------------------
extern "C" void kernel_launch(void* const* d_in, const int* in_sizes, int n_in,
                              void* d_out, int out_size) {
    const float* enc = (const float*)d_in[0];  // [B,TE,H]
    const float* dec = (const float*)d_in[1];  // [B,TD,H]
    const float* W   = (const float*)d_in[2];  // [H,H]
    const float* U   = (const float*)d_in[3];  // [H,H]
    const float* V   = (const float*)d_in[4];  // [H,1]

    float* c_out = (float*)d_out;              // [B,TD,H]
    float* e_out = (float*)d_out + B * TD * H; // [B,TD,TE]

    init_kernel<<<1, 32>>>();
    attn_static<<<NBLK, 256>>>(enc, dec, W, U, V, c_out, e_out);
}